// round 16
// baseline (speedup 1.0000x reference)
#include <cuda_runtime.h>
#include <cuda_bf16.h>
#include <cstdint>

#define D_FEAT    128
#define OUT_DIM   128
#define MAX_NODES 100000
#define MAX_EDGES 600000
#define SCAN_BLK  1024
#define CNT_PAD   102400

#define TM   64           // rows per GEMM tile
#define LDA  136          // padded bf16 row (272 B stride)
#define GT   256          // GEMM threads (8 warps)

// ---- device scratch (allocation-free) ----
// h and x stored as bf16 hi/lo images: per node 64 uint2 (32 hi, 32 lo) = 512 B
__device__ uint2 g_himg[(size_t)MAX_NODES * 64];
__device__ uint2 g_ximg[(size_t)MAX_NODES * 64];
__device__ __align__(16) int g_cnt[CNT_PAD];   // zero-init; self-cleaned each run
__device__ int   g_off[MAX_NODES + 1];
__device__ int   g_cur[MAX_NODES];
__device__ int   g_bsum[128];
__device__ int2  g_edge[MAX_EDGES + 8];        // +8 pad (zero-init: col=0 safe)
__device__ int   g_bar_cnt;
__device__ int   g_bar_gen;
// bf16 hi/lo images of B chunks: [chunk][part][n=128][k padded to LDA]
__device__ uint4 g_Bimg4[2 * 4352];   // 2 x 69632 B

// ============================ PTX helpers =================================
__device__ __forceinline__ uint32_t smem_u32(const void* p) {
    uint32_t a;
    asm("{ .reg .u64 t; cvta.to.shared.u64 t, %1; cvt.u32.u64 %0, t; }" : "=r"(a) : "l"(p));
    return a;
}
__device__ __forceinline__ void ldsm4(uint32_t* r, uint32_t addr) {
    asm volatile("ldmatrix.sync.aligned.m8n8.x4.shared.b16 {%0,%1,%2,%3}, [%4];"
                 : "=r"(r[0]), "=r"(r[1]), "=r"(r[2]), "=r"(r[3]) : "r"(addr));
}
__device__ __forceinline__ void mma_bf16(float* d, const uint32_t* a,
                                         uint32_t b0, uint32_t b1) {
    asm volatile(
        "mma.sync.aligned.m16n8k16.row.col.f32.bf16.bf16.f32 "
        "{%0,%1,%2,%3}, {%4,%5,%6,%7}, {%8,%9}, {%0,%1,%2,%3};"
        : "+f"(d[0]), "+f"(d[1]), "+f"(d[2]), "+f"(d[3])
        : "r"(a[0]), "r"(a[1]), "r"(a[2]), "r"(a[3]), "r"(b0), "r"(b1));
}
__device__ __forceinline__ uint32_t bf16x2(float y, float x) {
    uint32_t r; asm("cvt.rn.bf16x2.f32 %0, %1, %2;" : "=r"(r) : "f"(y), "f"(x)); return r;
}
__device__ __forceinline__ void cpa16(uint32_t dst, const void* src) {
    asm volatile("cp.async.cg.shared.global [%0], [%1], 16;" :: "r"(dst), "l"(src));
}
__device__ __forceinline__ void cpa16z(uint32_t dst, const void* src, int valid) {
    int sz = valid ? 16 : 0;
    asm volatile("cp.async.cg.shared.global [%0], [%1], 16, %2;"
                 :: "r"(dst), "l"(src), "r"(sz));
}
__device__ __forceinline__ void cpa_commit() {
    asm volatile("cp.async.commit_group;" ::: "memory");
}
template <int N>
__device__ __forceinline__ void cpa_wait() {
    asm volatile("cp.async.wait_group %0;" :: "n"(N) : "memory");
}

// ---- software grid barrier (all blocks co-resident: nb <= 148) ----
__device__ __forceinline__ void grid_bar(int nb) {
    __syncthreads();
    if (threadIdx.x == 0) {
        __threadfence();
        int gen = *(volatile int*)&g_bar_gen;
        if (atomicAdd(&g_bar_cnt, 1) == nb - 1) {
            g_bar_cnt = 0;
            __threadfence();
            *(volatile int*)&g_bar_gen = gen + 1;
        } else {
            while (*(volatile int*)&g_bar_gen == gen) { }
        }
        __threadfence();
    }
    __syncthreads();
}

// ======= prep: edge histogram + B image + x bf16 hi/lo image ==============
__global__ void hist_prep_kernel(const int*   __restrict__ rows,
                                 const float* __restrict__ W,
                                 const float* __restrict__ x,
                                 int n, int n_edges) {
    int i = blockIdx.x * blockDim.x + threadIdx.x;
    // x image: 32 threads per node (one float4 each)
    if (i < n * 32) {
        int nd = i >> 5;
        int l  = i & 31;
        float4 v = ((const float4*)(x + (size_t)nd * D_FEAT))[l];
        uint32_t h01 = bf16x2(v.y, v.x);
        uint32_t h23 = bf16x2(v.w, v.z);
        float fx = __uint_as_float(h01 << 16);
        float fy = __uint_as_float(h01 & 0xffff0000u);
        float fz = __uint_as_float(h23 << 16);
        float fw = __uint_as_float(h23 & 0xffff0000u);
        uint32_t l01 = bf16x2(v.y - fy, v.x - fx);
        uint32_t l23 = bf16x2(v.w - fw, v.z - fz);
        g_ximg[(size_t)nd * 64 + l]      = make_uint2(h01, h23);
        g_ximg[(size_t)nd * 64 + 32 + l] = make_uint2(l01, l23);
    }
    if (i < 2 * 128 * 128) {
        int c = i >> 14;
        int r = i & 16383;
        int k = r >> 7;
        int nn = r & 127;
        float w = W[(size_t)(c * 128 + k) * OUT_DIM + nn];
        __nv_bfloat16 hb = __float2bfloat16(w);
        __nv_bfloat16 lb = __float2bfloat16(w - __bfloat162float(hb));
        __nv_bfloat16* img = (__nv_bfloat16*)g_Bimg4;
        img[(((size_t)c * 2 + 0) * 128 + nn) * LDA + k] = hb;
        img[(((size_t)c * 2 + 1) * 128 + nn) * LDA + k] = lb;
    }
    if (i < n_edges) atomicAdd(&g_cnt[rows[i]], 1);
}

// ====== fused scan: per-block totals | grid barrier | base + full scan =====
__global__ __launch_bounds__(SCAN_BLK, 1)
void scan_fused_kernel(int n, int nb, int n_edges) {
    __shared__ int wsum[32];
    __shared__ int sbase;
    const int t    = threadIdx.x;
    const int lane = t & 31;
    const int w    = t >> 5;
    const int i    = blockIdx.x * SCAN_BLK + t;

    int v = (i < n) ? g_cnt[i] : 0;
    int s = v;
#pragma unroll
    for (int d = 1; d < 32; d <<= 1) {
        int q = __shfl_up_sync(~0u, s, d);
        if (lane >= d) s += q;
    }
    if (lane == 31) wsum[w] = s;
    __syncthreads();
    if (w == 0) {
        int q = wsum[lane];
#pragma unroll
        for (int d = 1; d < 32; d <<= 1) {
            int r = __shfl_up_sync(~0u, q, d);
            if (lane >= d) q += r;
        }
        wsum[lane] = q;
    }
    __syncthreads();
    int wbase  = (w > 0) ? wsum[w - 1] : 0;
    int s_incl = wbase + s;
    if (t == SCAN_BLK - 1) g_bsum[blockIdx.x] = s_incl;

    grid_bar(nb);

    if (w == 0) {
        int b = 0;
        for (int j = lane; j < (int)blockIdx.x; j += 32) b += g_bsum[j];
#pragma unroll
        for (int o = 16; o > 0; o >>= 1) b += __shfl_xor_sync(~0u, b, o);
        if (lane == 0) sbase = b;
    }
    __syncthreads();
    if (i < n) {
        int o = sbase + s_incl - v;
        g_off[i] = o;
        g_cur[i] = o;
        g_cnt[i] = 0;
    }
    if (i == n) g_off[n] = n_edges;
}

// ============ scatter: 1 edge/thread, max grid parallelism =================
__global__ void scatter_kernel(const int* __restrict__ rows,
                               const int* __restrict__ cols,
                               const float* __restrict__ vals,
                               int n_edges) {
    int i = blockIdx.x * blockDim.x + threadIdx.x;
    if (i < n_edges) {
        int r = rows[i];
        int p = atomicAdd(&g_cur[r], 1);
        g_edge[p] = make_int2(cols[i], __float_as_int(vals[i]));
    }
}

// ====== SpMM: 1 row/warp, batch-4 unconditional gathers (MLP=4) ===========
__global__ void spmm_csr_kernel(const float* __restrict__ x, int n_nodes) {
    int row  = (blockIdx.x * blockDim.x + threadIdx.x) >> 5;
    int lane = threadIdx.x & 31;
    if (row >= n_nodes) return;

    int e0 = g_off[row];
    int e1 = g_off[row + 1];

    float4 a0 = make_float4(0.f, 0.f, 0.f, 0.f);
    float4 a1 = make_float4(0.f, 0.f, 0.f, 0.f);

    for (int e = e0; e < e1; e += 4) {
        int2 ev0 = g_edge[e];
        int2 ev1 = g_edge[e + 1];
        int2 ev2 = g_edge[e + 2];
        int2 ev3 = g_edge[e + 3];
        if (e + 1 >= e1) ev1.y = 0;
        if (e + 2 >= e1) ev2.y = 0;
        if (e + 3 >= e1) ev3.y = 0;
        float4 x0 = ((const float4*)(x + (size_t)ev0.x * D_FEAT))[lane];
        float4 x1 = ((const float4*)(x + (size_t)ev1.x * D_FEAT))[lane];
        float4 x2 = ((const float4*)(x + (size_t)ev2.x * D_FEAT))[lane];
        float4 x3 = ((const float4*)(x + (size_t)ev3.x * D_FEAT))[lane];
        float v0 = __int_as_float(ev0.y), v1 = __int_as_float(ev1.y);
        float v2 = __int_as_float(ev2.y), v3 = __int_as_float(ev3.y);
        a0.x = fmaf(v0, x0.x, a0.x); a0.y = fmaf(v0, x0.y, a0.y);
        a0.z = fmaf(v0, x0.z, a0.z); a0.w = fmaf(v0, x0.w, a0.w);
        a1.x = fmaf(v1, x1.x, a1.x); a1.y = fmaf(v1, x1.y, a1.y);
        a1.z = fmaf(v1, x1.z, a1.z); a1.w = fmaf(v1, x1.w, a1.w);
        a0.x = fmaf(v2, x2.x, a0.x); a0.y = fmaf(v2, x2.y, a0.y);
        a0.z = fmaf(v2, x2.z, a0.z); a0.w = fmaf(v2, x2.w, a0.w);
        a1.x = fmaf(v3, x3.x, a1.x); a1.y = fmaf(v3, x3.y, a1.y);
        a1.z = fmaf(v3, x3.z, a1.z); a1.w = fmaf(v3, x3.w, a1.w);
    }

    float4 h = make_float4(a0.x + a1.x, a0.y + a1.y, a0.z + a1.z, a0.w + a1.w);
    uint32_t h01 = bf16x2(h.y, h.x);
    uint32_t h23 = bf16x2(h.w, h.z);
    float fx = __uint_as_float(h01 << 16);
    float fy = __uint_as_float(h01 & 0xffff0000u);
    float fz = __uint_as_float(h23 << 16);
    float fw = __uint_as_float(h23 & 0xffff0000u);
    uint32_t l01 = bf16x2(h.y - fy, h.x - fx);
    uint32_t l23 = bf16x2(h.w - fw, h.z - fz);
    g_himg[(size_t)row * 64 + lane]      = make_uint2(h01, h23);
    g_himg[(size_t)row * 64 + 32 + lane] = make_uint2(l01, l23);
}

// ====== persistent GEMM: out = relu([h|x] @ W) =============================
// 1 CTA/SM; B hi/lo for BOTH chunks loaded once; A double-buffered cp.async
// smem: A buf0 (34816: hi 17408 | lo 17408) | A buf1 (34816) | B (139264)
#define ABUF      34816
#define APART     17408
#define SMB       69632
#define SM_TOTAL  208896

__global__ __launch_bounds__(GT, 1)
void gemm_persist_kernel(float* __restrict__ out, int n_nodes, int ntiles) {
    extern __shared__ char smem[];
    const uint32_t sbase = smem_u32(smem);
    const int tid  = threadIdx.x;
    const int wid  = tid >> 5;
    const int lane = tid & 31;
    const int wm   = wid >> 2;      // 0..1
    const int wn   = wid & 3;       // 0..3

    // ldsm offsets (relative to buffer/chunk base)
    uint32_t pAo[2], pBo[2];
#pragma unroll
    for (int mf = 0; mf < 2; mf++)
        pAo[mf] = (uint32_t)((wm * 32 + mf * 16 + (lane & 15)) * (LDA * 2))
                + (uint32_t)((lane >> 4) << 4);
#pragma unroll
    for (int p = 0; p < 2; p++)
        pBo[p] = (uint32_t)((wn * 32 + p * 16 + (lane & 7) + ((lane >> 4) << 3)) * (LDA * 2))
               + (uint32_t)((lane & 8) << 1);

    // ---- one-time B load (both chunks, hi+lo = 8704 uint4) ----
#pragma unroll
    for (int j = tid; j < 8704; j += GT)
        cpa16(sbase + SMB + j * 16, g_Bimg4 + j);

    // ---- stage helper (as lambda-ish macro): chunk image -> A buffer ----
    auto stage_A = [&](int buf, int tile, int c) {
        const uint2* img = c ? g_ximg : g_himg;
        int row0 = tile * TM;
#pragma unroll
        for (int j = 0; j < 2048 / GT; j++) {        // 8 per thread
            int i    = tid + j * GT;
            int r    = i >> 5;
            int part = (i >> 4) & 1;
            int kq   = i & 15;
            int gr   = row0 + r;
            uint32_t dst = sbase + buf * ABUF + part * APART
                         + (uint32_t)(r * (LDA * 2) + kq * 16);
            const char* src = (const char*)(img + (size_t)gr * 64 + part * 32)
                            + kq * 16;
            cpa16z(dst, src, gr < n_nodes);
        }
    };

    // prefetch step 0 (tile = blockIdx.x, chunk 0)
    if ((int)blockIdx.x < ntiles) stage_A(0, blockIdx.x, 0);
    cpa_commit();
    cpa_wait<0>();
    __syncthreads();

    float acc[2][4][4];

    for (int s = 0; ; s++) {
        int tile = blockIdx.x + (s >> 1) * gridDim.x;
        if (tile >= ntiles) break;
        int c   = s & 1;
        int buf = s & 1;

        if (c == 0) {
#pragma unroll
            for (int mf = 0; mf < 2; mf++)
#pragma unroll
                for (int nf = 0; nf < 4; nf++)
#pragma unroll
                    for (int q = 0; q < 4; q++) acc[mf][nf][q] = 0.f;
        }

        // prefetch next chunk-step into the other buffer
        {
            int s1 = s + 1;
            int t1 = blockIdx.x + (s1 >> 1) * gridDim.x;
            if (t1 < ntiles) stage_A(buf ^ 1, t1, s1 & 1);
            cpa_commit();
        }

        // ---- MMA on current buffer / B chunk c ----
        const uint32_t abase = sbase + buf * ABUF;
        const uint32_t bbase = sbase + SMB + (uint32_t)c * 69632u;
#pragma unroll
        for (int ks = 0; ks < 8; ks++) {
            const uint32_t k0b = (uint32_t)(ks << 5);
            uint32_t Ah[2][4], Al[2][4];
#pragma unroll
            for (int mf = 0; mf < 2; mf++) {
                ldsm4(Ah[mf], abase + pAo[mf] + k0b);
                ldsm4(Al[mf], abase + APART + pAo[mf] + k0b);
            }
#pragma unroll
            for (int p = 0; p < 2; p++) {
                uint32_t Bh[4], Bl[4];
                ldsm4(Bh, bbase + pBo[p] + k0b);
                ldsm4(Bl, bbase + 34816 + pBo[p] + k0b);
#pragma unroll
                for (int mf = 0; mf < 2; mf++) {
                    float* a0 = acc[mf][2 * p];
                    float* a1 = acc[mf][2 * p + 1];
                    mma_bf16(a0, Ah[mf], Bh[0], Bh[1]);
                    mma_bf16(a1, Ah[mf], Bh[2], Bh[3]);
                    mma_bf16(a0, Al[mf], Bh[0], Bh[1]);
                    mma_bf16(a1, Al[mf], Bh[2], Bh[3]);
                    mma_bf16(a0, Ah[mf], Bl[0], Bl[1]);
                    mma_bf16(a1, Ah[mf], Bl[2], Bl[3]);
                }
            }
        }

        cpa_wait<0>();
        __syncthreads();

        if (c == 1) {
            // ---- epilogue: relu + store ----
            int row0 = tile * TM;
#pragma unroll
            for (int mf = 0; mf < 2; mf++) {
                int r0 = row0 + wm * 32 + mf * 16 + (lane >> 2);
                int r1 = r0 + 8;
#pragma unroll
                for (int nf = 0; nf < 4; nf++) {
                    int col = wn * 32 + nf * 8 + (lane & 3) * 2;
                    float* a = acc[mf][nf];
                    if (r0 < n_nodes) {
                        float2 o = make_float2(fmaxf(a[0], 0.f), fmaxf(a[1], 0.f));
                        *(float2*)(out + (size_t)r0 * OUT_DIM + col) = o;
                    }
                    if (r1 < n_nodes) {
                        float2 o = make_float2(fmaxf(a[2], 0.f), fmaxf(a[3], 0.f));
                        *(float2*)(out + (size_t)r1 * OUT_DIM + col) = o;
                    }
                }
            }
        }
    }
}

// ============================== launch =====================================
extern "C" void kernel_launch(void* const* d_in, const int* in_sizes, int n_in,
                              void* d_out, int out_size) {
    const float* x    = (const float*)d_in[0];
    const int*   rows = (const int*)  d_in[1];
    const int*   cols = (const int*)  d_in[2];
    const float* vals = (const float*)d_in[3];
    const float* W    = (const float*)d_in[4];
    float*       out  = (float*)d_out;

    const int n_nodes = in_sizes[0] / D_FEAT;
    const int n_edges = in_sizes[1];
    const int nb      = (n_nodes + SCAN_BLK - 1) / SCAN_BLK;   // 98 <= 148

    // prep needs n_nodes*32 threads for the x image
    int prep_threads = n_nodes * 32;
    if (prep_threads < n_edges) prep_threads = n_edges;
    hist_prep_kernel<<<(prep_threads + 255) / 256, 256>>>(rows, W, x, n_nodes, n_edges);

    scan_fused_kernel<<<nb, SCAN_BLK>>>(n_nodes, nb, n_edges);
    scatter_kernel<<<(n_edges + 255) / 256, 256>>>(rows, cols, vals, n_edges);

    long long spmm_threads = (long long)n_nodes * 32;
    spmm_csr_kernel<<<(int)((spmm_threads + 255) / 256), 256>>>(x, n_nodes);

    int nsm = 148;
    cudaDeviceGetAttribute(&nsm, cudaDevAttrMultiProcessorCount, 0);
    int ntiles = (n_nodes + TM - 1) / TM;
    cudaFuncSetAttribute(gemm_persist_kernel,
                         cudaFuncAttributeMaxDynamicSharedMemorySize, SM_TOTAL);
    gemm_persist_kernel<<<nsm, GT, SM_TOTAL>>>(out, n_nodes, ntiles);
}